// round 10
// baseline (speedup 1.0000x reference)
#include <cuda_runtime.h>
#include <cstdint>

// ============================================================================
// FrameAugment: out[b,i,f] = softmax_j(noise[b,i,j]*s[b,i]) @ feature[b,j,f]
//   s = (1/(var_row+1e-6)) / max_all(1/(var+1e-6)),  var ddof=1 over F.
// sm_103 baseline-PTX: fused exp + legacy tf32 mma.sync.m16n8k8.
// R10: noise + featT both streamed via cp.async rings (depth 3, lookahead 2)
//      so DRAM latency never touches the critical path; 128-row i-tiles
//      (128 CTAs x 512 thr) halve F L2 traffic; one barrier per stage.
// ============================================================================

#define B_ 8
#define S_ 2048
#define F_ 128
#define KC 32
#define NSTAGES (S_ / KC)        // 64
#define IT_ROWS 128              // i-rows per CTA

#define PPAD 36                  // P tile pitch (floats), LDSM conflict-free
#define FTP  36                  // featT tile pitch (floats)
#define NPITCH 48                // raw-noise tile pitch (floats): LDS.128 phase-clean

#define P_BYTES (IT_ROWS * PPAD * 4)   // 18432
#define F_BYTES (F_ * FTP * 4)         // 18432
#define N_BYTES (IT_ROWS * NPITCH * 4) // 24576

#define SMEM_RS 0
#define SMEM_P  512                       // 2 bufs
#define SMEM_F  (SMEM_P + 2 * P_BYTES)    // 3 bufs
#define SMEM_N  (SMEM_F + 3 * F_BYTES)    // 3 slots
#define SMEM_TOTAL (SMEM_N + 3 * N_BYTES) // 166400 bytes

#define LOG2E 1.4426950408889634f

// ---------------------------------------------------------------------------
// scratch (zero-initialized at module load)
// ---------------------------------------------------------------------------
__device__ float g_featT[B_ * F_ * S_];  // [b][f][j], 8 MB
__device__ float g_sraw[B_ * S_];        // raw inverse variance per row
__device__ int   g_gmax;                 // float-as-int global max; atomicMax
                                         // monotonic+idempotent -> replay safe

// ---------------------------------------------------------------------------
// helpers
// ---------------------------------------------------------------------------
__device__ __forceinline__ uint32_t smem_u32(const void* p) {
    uint32_t a;
    asm("{ .reg .u64 t; cvta.to.shared.u64 t, %1; cvt.u32.u64 %0, t; }" : "=r"(a) : "l"(p));
    return a;
}

__device__ __forceinline__ float fast_ex2(float x) {
    float y;
    asm("ex2.approx.ftz.f32 %0, %1;" : "=f"(y) : "f"(x));
    return y;
}

__device__ __forceinline__ uint32_t f2tf32(float x) {
    uint32_t r;
    asm("cvt.rna.tf32.f32 %0, %1;" : "=r"(r) : "f"(x));
    return r;
}

__device__ __forceinline__ void mma_tf32(float* c, const uint32_t* a,
                                         uint32_t b0, uint32_t b1) {
    asm volatile(
        "mma.sync.aligned.m16n8k8.row.col.f32.tf32.tf32.f32 "
        "{%0,%1,%2,%3}, {%4,%5,%6,%7}, {%8,%9}, {%0,%1,%2,%3};"
        : "+f"(c[0]), "+f"(c[1]), "+f"(c[2]), "+f"(c[3])
        : "r"(a[0]), "r"(a[1]), "r"(a[2]), "r"(a[3]), "r"(b0), "r"(b1));
}

__device__ __forceinline__ void ldsm_x4(uint32_t* a, uint32_t addr) {
    asm volatile(
        "ldmatrix.sync.aligned.m8n8.x4.shared.b16 {%0,%1,%2,%3}, [%4];"
        : "=r"(a[0]), "=r"(a[1]), "=r"(a[2]), "=r"(a[3]) : "r"(addr));
}

__device__ __forceinline__ void cp_async16(uint32_t dst, const void* src) {
    asm volatile("cp.async.cg.shared.global [%0], [%1], 16;" :: "r"(dst), "l"(src));
}
#define CP_ASYNC_COMMIT() asm volatile("cp.async.commit_group;" ::: "memory")
#define CP_ASYNC_WAIT_1() asm volatile("cp.async.wait_group 1;" ::: "memory")

// ---------------------------------------------------------------------------
// Kernel 1: inverse variance, 8 rows per warp front-batched (MLP=8).
// ---------------------------------------------------------------------------
__global__ void __launch_bounds__(256) var_kernel(const float* __restrict__ feat) {
    int warp = blockIdx.x * 8 + (threadIdx.x >> 5);
    int lane = threadIdx.x & 31;
    int row0 = warp * 8;

    float4 v[8];
    #pragma unroll
    for (int g = 0; g < 8; g++)
        v[g] = reinterpret_cast<const float4*>(feat + (size_t)(row0 + g) * F_)[lane];

    float wm = 0.0f;
    float rres[8];
    #pragma unroll
    for (int g = 0; g < 8; g++) {
        float s1 = v[g].x + v[g].y + v[g].z + v[g].w;
        float s2 = v[g].x * v[g].x + v[g].y * v[g].y + v[g].z * v[g].z + v[g].w * v[g].w;
        #pragma unroll
        for (int o = 16; o; o >>= 1) {
            s1 += __shfl_xor_sync(0xFFFFFFFFu, s1, o);
            s2 += __shfl_xor_sync(0xFFFFFFFFu, s2, o);
        }
        float var = (s2 - s1 * s1 * (1.0f / 128.0f)) * (1.0f / 127.0f);  // ddof=1
        float r = 1.0f / (var + 1e-6f);
        rres[g] = r;
        wm = fmaxf(wm, r);
    }
    if (lane == 0) {
        #pragma unroll
        for (int g = 0; g < 8; g++) g_sraw[row0 + g] = rres[g];
        atomicMax(&g_gmax, __float_as_int(wm));   // positive floats: int order ok
    }
}

// ---------------------------------------------------------------------------
// Kernel 1b: transpose feature [b][j][f] -> g_featT [b][f][j]
// ---------------------------------------------------------------------------
__global__ void __launch_bounds__(256) transpose_kernel(const float* __restrict__ feat) {
    __shared__ float tile[32][33];
    int b  = blockIdx.z;
    int j0 = blockIdx.x * 32;
    int f0 = blockIdx.y * 32;
    int tx = threadIdx.x, ty = threadIdx.y;  // 32 x 8
    const float* src = feat + (size_t)b * (S_ * F_);
    #pragma unroll
    for (int k = 0; k < 32; k += 8)
        tile[ty + k][tx] = src[(size_t)(j0 + ty + k) * F_ + f0 + tx];
    __syncthreads();
    float* dst = g_featT + (size_t)b * (S_ * F_);
    #pragma unroll
    for (int k = 0; k < 32; k += 8)
        dst[(size_t)(f0 + ty + k) * S_ + j0 + tx] = tile[tx][ty + k];
}

// ---------------------------------------------------------------------------
// Kernel 2: fused exp + tf32 mma.sync GEMM.
// 128 CTAs = (b, 128-row i-tile). 512 threads = 16 warps (4 i x 4 f),
// warp tile 32i x 32f. Groups G(j)=[F(j), noise(j+1)] committed 2 stages
// ahead; per stage: commit G(kt+2), MMA(kt), stage P(kt+1) from noise SMEM,
// wait_group 1, one __syncthreads.
// ---------------------------------------------------------------------------
__global__ void __launch_bounds__(512, 1)
main_kernel(const float* __restrict__ noise, float* __restrict__ out) {
    extern __shared__ char smem[];
    float* rs_s = reinterpret_cast<float*>(smem + SMEM_RS);
    const uint32_t sbase = smem_u32(smem);
    const uint32_t Pbase = sbase + SMEM_P;
    const uint32_t Fbase = sbase + SMEM_F;
    const uint32_t Nbase = sbase + SMEM_N;

    const int tid  = threadIdx.x;
    const int lane = tid & 31;
    const int wid  = tid >> 5;        // 0..15
    const int wi   = wid >> 2;        // i block (32 rows): 0..3
    const int wf   = wid & 3;         // f block (32 cols): 0..3
    const int b    = blockIdx.x >> 4;
    const int i0   = (blockIdx.x & 15) * IT_ROWS;

    // uniform staging map: thread owns row (tid>>2), 16B chunks cq and cq+4
    const int prow = tid >> 2;        // 0..127
    const int cq   = tid & 3;         // 0..3

    // SMEM offsets (bytes, buffer-relative)
    const uint32_t n_off0 = (uint32_t)((prow * NPITCH + cq * 4) * 4);
    const uint32_t n_off1 = n_off0 + 64;
    const uint32_t f_off0 = (uint32_t)((prow * FTP + cq * 4) * 4);
    const uint32_t f_off1 = f_off0 + 64;
    const uint32_t p_off0 = (uint32_t)((prow * PPAD + cq * 4) * 4);
    const uint32_t p_off1 = p_off0 + 64;

    // global sources
    const float* nsrc = noise + ((size_t)(b * S_ + i0 + prow)) * S_ + cq * 4;
    const float* fsrc = g_featT + (size_t)b * (F_ * S_) + (size_t)prow * S_ + cq * 4;

    const float sl = g_sraw[b * S_ + i0 + prow] *
                     (1.0f / __int_as_float(g_gmax)) * LOG2E;
    float rs = 0.0f;

    // MMA fragment lane offsets
    const uint32_t a_lane_off =
        (uint32_t)(((wi * 32 + (lane & 15)) * PPAD + (lane >> 4) * 4) * 4);
    const uint32_t b_lane_off =
        (uint32_t)(((wf * 32 + (lane & 7)) * FTP) * 4 + (lane >> 3) * 16);

    float acc[2][4][4];
    #pragma unroll
    for (int it = 0; it < 2; it++)
        #pragma unroll
        for (int ft = 0; ft < 4; ft++)
            #pragma unroll
            for (int c = 0; c < 4; c++) acc[it][ft][c] = 0.0f;

    // ---- group issue: G(j) = [F(j) -> fbuf j%3, noise(j+1) -> nslot (j+1)%3]
    auto issue_group = [&](int j) {
        if (j < NSTAGES) {
            const uint32_t fb = Fbase + (uint32_t)(j % 3) * F_BYTES;
            cp_async16(fb + f_off0, fsrc + (size_t)j * KC);
            cp_async16(fb + f_off1, fsrc + (size_t)j * KC + 16);
        }
        if (j + 1 < NSTAGES) {
            const uint32_t nb = Nbase + (uint32_t)((j + 1) % 3) * N_BYTES;
            cp_async16(nb + n_off0, nsrc + (size_t)(j + 1) * KC);
            cp_async16(nb + n_off1, nsrc + (size_t)(j + 1) * KC + 16);
        }
        CP_ASYNC_COMMIT();
    };

    // ---- stage P(j): read noise slot j%3 from SMEM, exp, store to P buf j&1
    auto stage_P = [&](int j) {
        const uint32_t nb = Nbase + (uint32_t)(j % 3) * N_BYTES;
        float4 v0, v1;
        asm volatile("ld.shared.v4.f32 {%0,%1,%2,%3}, [%4];"
                     : "=f"(v0.x), "=f"(v0.y), "=f"(v0.z), "=f"(v0.w)
                     : "r"(nb + n_off0));
        asm volatile("ld.shared.v4.f32 {%0,%1,%2,%3}, [%4];"
                     : "=f"(v1.x), "=f"(v1.y), "=f"(v1.z), "=f"(v1.w)
                     : "r"(nb + n_off1));
        uint4 t0, t1;
        t0.x = f2tf32(fast_ex2(v0.x * sl)); t0.y = f2tf32(fast_ex2(v0.y * sl));
        t0.z = f2tf32(fast_ex2(v0.z * sl)); t0.w = f2tf32(fast_ex2(v0.w * sl));
        t1.x = f2tf32(fast_ex2(v1.x * sl)); t1.y = f2tf32(fast_ex2(v1.y * sl));
        t1.z = f2tf32(fast_ex2(v1.z * sl)); t1.w = f2tf32(fast_ex2(v1.w * sl));
        rs += (__uint_as_float(t0.x) + __uint_as_float(t0.y)) +
              (__uint_as_float(t0.z) + __uint_as_float(t0.w)) +
              (__uint_as_float(t1.x) + __uint_as_float(t1.y)) +
              (__uint_as_float(t1.z) + __uint_as_float(t1.w));
        const uint32_t pb = Pbase + (uint32_t)(j & 1) * P_BYTES;
        asm volatile("st.shared.v4.b32 [%0], {%1,%2,%3,%4};"
                     :: "r"(pb + p_off0), "r"(t0.x), "r"(t0.y), "r"(t0.z), "r"(t0.w));
        asm volatile("st.shared.v4.b32 [%0], {%1,%2,%3,%4};"
                     :: "r"(pb + p_off1), "r"(t1.x), "r"(t1.y), "r"(t1.z), "r"(t1.w));
    };

    // ---- prologue ----
    {   // G_pre = [noise(0) -> slot 0]
        const uint32_t nb = Nbase;  // slot 0
        cp_async16(nb + n_off0, nsrc);
        cp_async16(nb + n_off1, nsrc + 16);
        CP_ASYNC_COMMIT();
    }
    issue_group(0);          // F(0), n(1)
    CP_ASYNC_WAIT_1();       // forces G_pre (n(0))
    __syncthreads();
    stage_P(0);
    issue_group(1);          // F(1), n(2)
    CP_ASYNC_WAIT_1();       // forces G(0): F(0), n(1)
    __syncthreads();

    // ---- mainloop ----
    for (int kt = 0; kt < NSTAGES; kt++) {
        issue_group(kt + 2);

        // MMA(kt)
        {
            const uint32_t Pa = Pbase + (uint32_t)(kt & 1) * P_BYTES + a_lane_off;
            const uint32_t Fa = Fbase + (uint32_t)(kt % 3) * F_BYTES + b_lane_off;
            uint32_t A[2][4][4];
            #pragma unroll
            for (int it = 0; it < 2; it++)
                #pragma unroll
                for (int s = 0; s < 4; s++)
                    ldsm_x4(A[it][s], Pa + (uint32_t)(it * 16 * PPAD * 4 + s * 32));
            #pragma unroll
            for (int ft = 0; ft < 4; ft++) {
                #pragma unroll
                for (int pr = 0; pr < 2; pr++) {
                    uint32_t bb[4];
                    ldsm_x4(bb, Fa + (uint32_t)(ft * 8 * FTP * 4 + pr * 64));
                    #pragma unroll
                    for (int it = 0; it < 2; it++) {
                        mma_tf32(acc[it][ft], A[it][2 * pr],     bb[0], bb[1]);
                        mma_tf32(acc[it][ft], A[it][2 * pr + 1], bb[2], bb[3]);
                    }
                }
            }
        }

        if (kt + 1 < NSTAGES) stage_P(kt + 1);

        CP_ASYNC_WAIT_1();   // forces G(kt+1): F(kt+1), n(kt+2)
        __syncthreads();
    }

    // ---- row sums: 4 threads share a row ----
    rs += __shfl_xor_sync(0xFFFFFFFFu, rs, 1);
    rs += __shfl_xor_sync(0xFFFFFFFFu, rs, 2);
    if (cq == 0) rs_s[prow] = rs;
    __syncthreads();

    // ---- epilogue ----
    #pragma unroll
    for (int it = 0; it < 2; it++) {
        const int r0 = wi * 32 + it * 16 + (lane >> 2);
        const int r1 = r0 + 8;
        const float inv0 = 1.0f / rs_s[r0];
        const float inv1 = 1.0f / rs_s[r1];
        float* o0 = out + (size_t)(b * S_ + i0 + r0) * F_;
        float* o1 = out + (size_t)(b * S_ + i0 + r1) * F_;
        #pragma unroll
        for (int ft = 0; ft < 4; ft++) {
            const int n = wf * 32 + ft * 8 + (lane & 3) * 2;
            float2 v0 = { acc[it][ft][0] * inv0, acc[it][ft][1] * inv0 };
            float2 v1 = { acc[it][ft][2] * inv1, acc[it][ft][3] * inv1 };
            *reinterpret_cast<float2*>(o0 + n) = v0;
            *reinterpret_cast<float2*>(o1 + n) = v1;
        }
    }
}

// ---------------------------------------------------------------------------
// launch
// ---------------------------------------------------------------------------
extern "C" void kernel_launch(void* const* d_in, const int* in_sizes, int n_in,
                              void* d_out, int out_size) {
    static bool attr_set = false;
    if (!attr_set) {
        cudaFuncSetAttribute(main_kernel,
                             cudaFuncAttributeMaxDynamicSharedMemorySize, SMEM_TOTAL);
        attr_set = true;
    }

    const float* feature = (const float*)d_in[0];
    const float* noise   = (const float*)d_in[1];
    if (n_in >= 2 && in_sizes[0] > in_sizes[1]) {
        feature = (const float*)d_in[1];
        noise   = (const float*)d_in[0];
    }
    float* out = (float*)d_out;

    var_kernel<<<(B_ * S_) / 64, 256>>>(feature);
    transpose_kernel<<<dim3(S_ / 32, F_ / 32, B_), dim3(32, 8)>>>(feature);
    main_kernel<<<B_ * (S_ / IT_ROWS), 512, SMEM_TOTAL>>>(noise, out);
}

// round 11
// speedup vs baseline: 1.5084x; 1.5084x over previous
#include <cuda_runtime.h>
#include <cuda_fp16.h>
#include <cstdint>

// ============================================================================
// FrameAugment: out[b,i,f] = softmax_j(noise[b,i,j]*s[b,i]) @ feature[b,j,f]
//   s = (1/(var_row+1e-6)) / max_all(1/(var+1e-6)),  var ddof=1 over F.
// sm_103 baseline-PTX. R11: fp16 m16n8k16 mma.sync (same 10-bit mantissa as
// tf32 -> same accuracy, HALF the HMMA+LDSM instruction stream), fp16 featT
// (halves F traffic/SMEM), cp.async rings for noise + featT kept from R10.
// ============================================================================

#define B_ 8
#define S_ 2048
#define F_ 128
#define KC 32
#define NSTAGES (S_ / KC)        // 64
#define IT_ROWS 128              // i-rows per CTA

#define PPITCH_B 80              // P fp16 tile row pitch bytes (32 k + pad)
#define FPITCH_B 80              // featT fp16 tile row pitch bytes
#define NPITCH   48              // raw-noise pitch (floats)

#define P_BYTES (IT_ROWS * PPITCH_B)    // 10240
#define F_BYTES (F_ * FPITCH_B)         // 10240
#define N_BYTES (IT_ROWS * NPITCH * 4)  // 24576

#define SMEM_RS 0
#define SMEM_P  512                        // 2 bufs
#define SMEM_F  (SMEM_P + 2 * P_BYTES)     // 3 bufs
#define SMEM_N  (SMEM_F + 3 * F_BYTES)     // 3 slots
#define SMEM_TOTAL (SMEM_N + 3 * N_BYTES)  // 125440 bytes

#define LOG2E 1.4426950408889634f

// ---------------------------------------------------------------------------
// scratch (zero-initialized at module load)
// ---------------------------------------------------------------------------
__device__ __half g_featT[B_ * F_ * S_];  // [b][f][j] fp16, 4 MB
__device__ float  g_sraw[B_ * S_];        // raw inverse variance per row
__device__ int    g_gmax;                 // float-as-int global max; atomicMax
                                          // monotonic+idempotent -> replay safe

// ---------------------------------------------------------------------------
// helpers
// ---------------------------------------------------------------------------
__device__ __forceinline__ uint32_t smem_u32(const void* p) {
    uint32_t a;
    asm("{ .reg .u64 t; cvta.to.shared.u64 t, %1; cvt.u32.u64 %0, t; }" : "=r"(a) : "l"(p));
    return a;
}

__device__ __forceinline__ float fast_ex2(float x) {
    float y;
    asm("ex2.approx.ftz.f32 %0, %1;" : "=f"(y) : "f"(x));
    return y;
}

__device__ __forceinline__ uint32_t pack_h2(float lo, float hi) {
    __half2 h = __floats2half2_rn(lo, hi);   // .x = lo (low 16 bits)
    return *reinterpret_cast<uint32_t*>(&h);
}

// D[16,8] += A[16,16] * B[16,8], fp16 inputs, fp32 accumulate
__device__ __forceinline__ void mma_f16(float* c, const uint32_t* a,
                                        uint32_t b0, uint32_t b1) {
    asm volatile(
        "mma.sync.aligned.m16n8k16.row.col.f32.f16.f16.f32 "
        "{%0,%1,%2,%3}, {%4,%5,%6,%7}, {%8,%9}, {%0,%1,%2,%3};"
        : "+f"(c[0]), "+f"(c[1]), "+f"(c[2]), "+f"(c[3])
        : "r"(a[0]), "r"(a[1]), "r"(a[2]), "r"(a[3]), "r"(b0), "r"(b1));
}

__device__ __forceinline__ void ldsm_x4(uint32_t* a, uint32_t addr) {
    asm volatile(
        "ldmatrix.sync.aligned.m8n8.x4.shared.b16 {%0,%1,%2,%3}, [%4];"
        : "=r"(a[0]), "=r"(a[1]), "=r"(a[2]), "=r"(a[3]) : "r"(addr));
}

__device__ __forceinline__ void cp_async16(uint32_t dst, const void* src) {
    asm volatile("cp.async.cg.shared.global [%0], [%1], 16;" :: "r"(dst), "l"(src));
}
#define CP_ASYNC_COMMIT() asm volatile("cp.async.commit_group;" ::: "memory")
#define CP_ASYNC_WAIT_1() asm volatile("cp.async.wait_group 1;" ::: "memory")

// ---------------------------------------------------------------------------
// Kernel 1: inverse variance, 8 rows per warp front-batched (MLP=8).
// ---------------------------------------------------------------------------
__global__ void __launch_bounds__(256) var_kernel(const float* __restrict__ feat) {
    int warp = blockIdx.x * 8 + (threadIdx.x >> 5);
    int lane = threadIdx.x & 31;
    int row0 = warp * 8;

    float4 v[8];
    #pragma unroll
    for (int g = 0; g < 8; g++)
        v[g] = reinterpret_cast<const float4*>(feat + (size_t)(row0 + g) * F_)[lane];

    float wm = 0.0f;
    float rres[8];
    #pragma unroll
    for (int g = 0; g < 8; g++) {
        float s1 = v[g].x + v[g].y + v[g].z + v[g].w;
        float s2 = v[g].x * v[g].x + v[g].y * v[g].y + v[g].z * v[g].z + v[g].w * v[g].w;
        #pragma unroll
        for (int o = 16; o; o >>= 1) {
            s1 += __shfl_xor_sync(0xFFFFFFFFu, s1, o);
            s2 += __shfl_xor_sync(0xFFFFFFFFu, s2, o);
        }
        float var = (s2 - s1 * s1 * (1.0f / 128.0f)) * (1.0f / 127.0f);  // ddof=1
        float r = 1.0f / (var + 1e-6f);
        rres[g] = r;
        wm = fmaxf(wm, r);
    }
    if (lane == 0) {
        #pragma unroll
        for (int g = 0; g < 8; g++) g_sraw[row0 + g] = rres[g];
        atomicMax(&g_gmax, __float_as_int(wm));   // positive floats: int order ok
    }
}

// ---------------------------------------------------------------------------
// Kernel 1b: transpose feature [b][j][f] -> g_featT [b][f][j] (fp16)
// ---------------------------------------------------------------------------
__global__ void __launch_bounds__(256) transpose_kernel(const float* __restrict__ feat) {
    __shared__ float tile[32][33];
    int b  = blockIdx.z;
    int j0 = blockIdx.x * 32;
    int f0 = blockIdx.y * 32;
    int tx = threadIdx.x, ty = threadIdx.y;  // 32 x 8
    const float* src = feat + (size_t)b * (S_ * F_);
    #pragma unroll
    for (int k = 0; k < 32; k += 8)
        tile[ty + k][tx] = src[(size_t)(j0 + ty + k) * F_ + f0 + tx];
    __syncthreads();
    __half* dst = g_featT + (size_t)b * (S_ * F_);
    #pragma unroll
    for (int k = 0; k < 32; k += 8)
        dst[(size_t)(f0 + ty + k) * S_ + j0 + tx] = __float2half_rn(tile[tx][ty + k]);
}

// ---------------------------------------------------------------------------
// Kernel 2: fused exp + fp16 mma.sync GEMM.
// 128 CTAs = (b, 128-row i-tile). 512 threads = 16 warps (4 i x 4 f),
// warp tile 32i x 32f. Per warp-stage: 4 A-LDSM + 4 B-LDSM + 16 HMMA.16816.
// Groups G(j)=[F(j), noise(j+1)] committed 2 stages ahead (cp.async ring).
// ---------------------------------------------------------------------------
__global__ void __launch_bounds__(512, 1)
main_kernel(const float* __restrict__ noise, float* __restrict__ out) {
    extern __shared__ char smem[];
    float* rs_s = reinterpret_cast<float*>(smem + SMEM_RS);
    const uint32_t sbase = smem_u32(smem);
    const uint32_t Pbase = sbase + SMEM_P;
    const uint32_t Fbase = sbase + SMEM_F;
    const uint32_t Nbase = sbase + SMEM_N;

    const int tid  = threadIdx.x;
    const int lane = tid & 31;
    const int wid  = tid >> 5;        // 0..15
    const int wi   = wid >> 2;        // i block (32 rows): 0..3
    const int wf   = wid & 3;         // f block (32 cols): 0..3
    const int b    = blockIdx.x >> 4;
    const int i0   = (blockIdx.x & 15) * IT_ROWS;

    // staging map: thread owns row (tid>>2), k-chunk of 8 (cq)
    const int prow = tid >> 2;        // 0..127
    const int cq   = tid & 3;         // 0..3

    // SMEM byte offsets (buffer-relative)
    const uint32_t n_off0 = (uint32_t)(prow * (NPITCH * 4) + cq * 32);
    const uint32_t n_off1 = n_off0 + 16;
    const uint32_t f_off  = (uint32_t)(prow * FPITCH_B + cq * 16);
    const uint32_t p_off  = (uint32_t)(prow * PPITCH_B + cq * 16);

    // global sources
    const float*  nsrc = noise + ((size_t)(b * S_ + i0 + prow)) * S_ + cq * 8;
    const __half* fsrc = g_featT + (size_t)b * (F_ * S_) + (size_t)prow * S_ + cq * 8;

    const float sl = g_sraw[b * S_ + i0 + prow] *
                     (1.0f / __int_as_float(g_gmax)) * LOG2E;
    float rs = 0.0f;

    // fragment lane offsets (fp16 m16n8k16; mat = lane>>3)
    // A: row = base + (l&7) + ((l>>3)&1)*8 ; kbyte = ((l>>4)&1)*16 (+ s*32)
    const uint32_t a_lane =
        (uint32_t)(((lane & 7) + ((lane >> 3) & 1) * 8) * PPITCH_B +
                   ((lane >> 4) & 1) * 16);
    // B: n = wf*32 + (l&7) + ((l>>4)&1)*8 ; kbyte = ((l>>3)&1)*16 (+ s*32)
    const uint32_t b_lane =
        (uint32_t)((wf * 32 + (lane & 7) + ((lane >> 4) & 1) * 8) * FPITCH_B +
                   ((lane >> 3) & 1) * 16);

    float acc[2][4][4];
    #pragma unroll
    for (int it = 0; it < 2; it++)
        #pragma unroll
        for (int nb = 0; nb < 4; nb++)
            #pragma unroll
            for (int c = 0; c < 4; c++) acc[it][nb][c] = 0.0f;

    // ---- group issue: G(j) = [F(j) -> fbuf j%3, noise(j+1) -> nslot (j+1)%3]
    auto issue_group = [&](int j) {
        if (j < NSTAGES) {
            const uint32_t fb = Fbase + (uint32_t)(j % 3) * F_BYTES;
            cp_async16(fb + f_off, fsrc + (size_t)j * KC);
        }
        if (j + 1 < NSTAGES) {
            const uint32_t nb = Nbase + (uint32_t)((j + 1) % 3) * N_BYTES;
            cp_async16(nb + n_off0, nsrc + (size_t)(j + 1) * KC);
            cp_async16(nb + n_off1, nsrc + (size_t)(j + 1) * KC + 4);
        }
        CP_ASYNC_COMMIT();
    };

    // ---- stage P(j): noise slot j%3 -> exp -> fp16 -> P buf j&1
    auto stage_P = [&](int j) {
        const uint32_t nb = Nbase + (uint32_t)(j % 3) * N_BYTES;
        float4 v0, v1;
        asm volatile("ld.shared.v4.f32 {%0,%1,%2,%3}, [%4];"
                     : "=f"(v0.x), "=f"(v0.y), "=f"(v0.z), "=f"(v0.w)
                     : "r"(nb + n_off0));
        asm volatile("ld.shared.v4.f32 {%0,%1,%2,%3}, [%4];"
                     : "=f"(v1.x), "=f"(v1.y), "=f"(v1.z), "=f"(v1.w)
                     : "r"(nb + n_off1));
        float e0 = fast_ex2(v0.x * sl), e1 = fast_ex2(v0.y * sl);
        float e2 = fast_ex2(v0.z * sl), e3 = fast_ex2(v0.w * sl);
        float e4 = fast_ex2(v1.x * sl), e5 = fast_ex2(v1.y * sl);
        float e6 = fast_ex2(v1.z * sl), e7 = fast_ex2(v1.w * sl);
        rs += ((e0 + e1) + (e2 + e3)) + ((e4 + e5) + (e6 + e7));
        uint32_t h0 = pack_h2(e0, e1), h1 = pack_h2(e2, e3);
        uint32_t h2 = pack_h2(e4, e5), h3 = pack_h2(e6, e7);
        const uint32_t pb = Pbase + (uint32_t)(j & 1) * P_BYTES;
        asm volatile("st.shared.v4.b32 [%0], {%1,%2,%3,%4};"
                     :: "r"(pb + p_off), "r"(h0), "r"(h1), "r"(h2), "r"(h3));
    };

    // ---- prologue ----
    {   // G_pre = [noise(0) -> slot 0]
        cp_async16(Nbase + n_off0, nsrc);
        cp_async16(Nbase + n_off1, nsrc + 4);
        CP_ASYNC_COMMIT();
    }
    issue_group(0);          // F(0), n(1)
    CP_ASYNC_WAIT_1();       // forces G_pre (n(0))
    __syncthreads();
    stage_P(0);
    issue_group(1);          // F(1), n(2)
    CP_ASYNC_WAIT_1();       // forces G(0): F(0), n(1)
    __syncthreads();

    // ---- mainloop ----
    for (int kt = 0; kt < NSTAGES; kt++) {
        issue_group(kt + 2);

        // MMA(kt): K=32 as two k16 steps
        {
            const uint32_t Pa = Pbase + (uint32_t)(kt & 1) * P_BYTES + a_lane
                              + (uint32_t)(wi * 32) * PPITCH_B;
            const uint32_t Fa = Fbase + (uint32_t)(kt % 3) * F_BYTES + b_lane;
            uint32_t A[2][2][4];
            #pragma unroll
            for (int it = 0; it < 2; it++)
                #pragma unroll
                for (int s = 0; s < 2; s++)
                    ldsm_x4(A[it][s], Pa + (uint32_t)(it * 16 * PPITCH_B + s * 32));
            #pragma unroll
            for (int p = 0; p < 2; p++) {        // n-block pairs (16 cols each)
                #pragma unroll
                for (int s = 0; s < 2; s++) {    // k16 steps
                    uint32_t bb[4];              // regs0,1: n-block 2p; 2,3: 2p+1
                    ldsm_x4(bb, Fa + (uint32_t)(p * 16 * FPITCH_B + s * 32));
                    #pragma unroll
                    for (int it = 0; it < 2; it++) {
                        mma_f16(acc[it][2 * p],     A[it][s], bb[0], bb[1]);
                        mma_f16(acc[it][2 * p + 1], A[it][s], bb[2], bb[3]);
                    }
                }
            }
        }

        if (kt + 1 < NSTAGES) stage_P(kt + 1);

        CP_ASYNC_WAIT_1();   // forces G(kt+1): F(kt+1), n(kt+2)
        __syncthreads();
    }

    // ---- row sums: 4 threads share a row ----
    rs += __shfl_xor_sync(0xFFFFFFFFu, rs, 1);
    rs += __shfl_xor_sync(0xFFFFFFFFu, rs, 2);
    if (cq == 0) rs_s[prow] = rs;
    __syncthreads();

    // ---- epilogue ----
    #pragma unroll
    for (int it = 0; it < 2; it++) {
        const int r0 = wi * 32 + it * 16 + (lane >> 2);
        const int r1 = r0 + 8;
        const float inv0 = 1.0f / rs_s[r0];
        const float inv1 = 1.0f / rs_s[r1];
        float* o0 = out + (size_t)(b * S_ + i0 + r0) * F_;
        float* o1 = out + (size_t)(b * S_ + i0 + r1) * F_;
        #pragma unroll
        for (int nb = 0; nb < 4; nb++) {
            const int n = wf * 32 + nb * 8 + (lane & 3) * 2;
            float2 v0 = { acc[it][nb][0] * inv0, acc[it][nb][1] * inv0 };
            float2 v1 = { acc[it][nb][2] * inv1, acc[it][nb][3] * inv1 };
            *reinterpret_cast<float2*>(o0 + n) = v0;
            *reinterpret_cast<float2*>(o1 + n) = v1;
        }
    }
}

// ---------------------------------------------------------------------------
// launch
// ---------------------------------------------------------------------------
extern "C" void kernel_launch(void* const* d_in, const int* in_sizes, int n_in,
                              void* d_out, int out_size) {
    static bool attr_set = false;
    if (!attr_set) {
        cudaFuncSetAttribute(main_kernel,
                             cudaFuncAttributeMaxDynamicSharedMemorySize, SMEM_TOTAL);
        attr_set = true;
    }

    const float* feature = (const float*)d_in[0];
    const float* noise   = (const float*)d_in[1];
    if (n_in >= 2 && in_sizes[0] > in_sizes[1]) {
        feature = (const float*)d_in[1];
        noise   = (const float*)d_in[0];
    }
    float* out = (float*)d_out;

    var_kernel<<<(B_ * S_) / 64, 256>>>(feature);
    transpose_kernel<<<dim3(S_ / 32, F_ / 32, B_), dim3(32, 8)>>>(feature);
    main_kernel<<<B_ * (S_ / IT_ROWS), 512, SMEM_TOTAL>>>(noise, out);
}

// round 13
// speedup vs baseline: 1.7478x; 1.1587x over previous
#include <cuda_runtime.h>
#include <cuda_fp16.h>
#include <cstdint>

// ============================================================================
// FrameAugment: out[b,i,f] = softmax_j(noise[b,i,j]*s[b,i]) @ feature[b,j,f]
//   s = (1/(var_row+1e-6)) / max_all(1/(var+1e-6)),  var ddof=1 over F.
// sm_103 baseline-PTX. R13 = R12 with the misalignment fixed:
//   - prep tile pitch 130 -> 132 floats (528B, 16B multiple) for float4 LDS
//   - g_featT explicitly 16B aligned for cp.async / uint4 stores
// Noise: 2-deep register prefetch. featT: cp.async ring depth 3. fp16 k16 MMA.
// ============================================================================

#define B_ 8
#define S_ 2048
#define F_ 128
#define KC 32
#define NSTAGES (S_ / KC)        // 64
#define IT_ROWS 128              // i-rows per CTA

#define PPITCH_B 80              // P fp16 tile row pitch bytes (32 k + pad)
#define FPITCH_B 80              // featT fp16 tile row pitch bytes

#define P_BYTES (IT_ROWS * PPITCH_B)    // 10240
#define F_BYTES (F_ * FPITCH_B)         // 10240

#define SMEM_RS 0
#define SMEM_P  512                        // 2 bufs
#define SMEM_F  (SMEM_P + 2 * P_BYTES)     // 3 bufs
#define SMEM_TOTAL (SMEM_F + 3 * F_BYTES)  // 51712 bytes

#define LOG2E 1.4426950408889634f

// ---------------------------------------------------------------------------
// scratch (zero-initialized at module load)
// ---------------------------------------------------------------------------
__device__ __align__(16) __half g_featT[B_ * F_ * S_];  // [b][f][j] fp16, 4 MB
__device__ float g_sraw[B_ * S_];   // raw inverse variance per row
__device__ int   g_gmax;            // float-as-int global max; atomicMax is
                                    // monotonic+idempotent -> graph-replay safe

// ---------------------------------------------------------------------------
// helpers
// ---------------------------------------------------------------------------
__device__ __forceinline__ uint32_t smem_u32(const void* p) {
    uint32_t a;
    asm("{ .reg .u64 t; cvta.to.shared.u64 t, %1; cvt.u32.u64 %0, t; }" : "=r"(a) : "l"(p));
    return a;
}

__device__ __forceinline__ float fast_ex2(float x) {
    float y;
    asm("ex2.approx.ftz.f32 %0, %1;" : "=f"(y) : "f"(x));
    return y;
}

__device__ __forceinline__ uint32_t pack_h2(float lo, float hi) {
    __half2 h = __floats2half2_rn(lo, hi);   // .x = lo (low 16 bits)
    return *reinterpret_cast<uint32_t*>(&h);
}

// D[16,8] += A[16,16] * B[16,8], fp16 inputs, fp32 accumulate
__device__ __forceinline__ void mma_f16(float* c, const uint32_t* a,
                                        uint32_t b0, uint32_t b1) {
    asm volatile(
        "mma.sync.aligned.m16n8k16.row.col.f32.f16.f16.f32 "
        "{%0,%1,%2,%3}, {%4,%5,%6,%7}, {%8,%9}, {%0,%1,%2,%3};"
        : "+f"(c[0]), "+f"(c[1]), "+f"(c[2]), "+f"(c[3])
        : "r"(a[0]), "r"(a[1]), "r"(a[2]), "r"(a[3]), "r"(b0), "r"(b1));
}

__device__ __forceinline__ void ldsm_x4(uint32_t* a, uint32_t addr) {
    asm volatile(
        "ldmatrix.sync.aligned.m8n8.x4.shared.b16 {%0,%1,%2,%3}, [%4];"
        : "=r"(a[0]), "=r"(a[1]), "=r"(a[2]), "=r"(a[3]) : "r"(addr));
}

__device__ __forceinline__ void cp_async16(uint32_t dst, const void* src) {
    asm volatile("cp.async.cg.shared.global [%0], [%1], 16;" :: "r"(dst), "l"(src));
}
#define CP_ASYNC_COMMIT() asm volatile("cp.async.commit_group;" ::: "memory")
#define CP_ASYNC_WAIT_1() asm volatile("cp.async.wait_group 1;" ::: "memory")

// ---------------------------------------------------------------------------
// Kernel 1 (fused): per-row inverse variance + fp16 transpose.
// Grid (S/32, B), 256 threads. Each CTA: 32 j-rows x 128 f through SMEM.
// Tile pitch 132 floats = 528B (16B multiple -> float4 LDS legal on all rows).
// ---------------------------------------------------------------------------
__global__ void __launch_bounds__(256) prep_kernel(const float* __restrict__ feat) {
    __shared__ float tile[32][132];
    const int t  = threadIdx.x;
    const int b  = blockIdx.y;
    const int j0 = blockIdx.x * 32;
    const int lane = t & 31;
    const int wrp  = t >> 5;

    // load 32 x 128 floats (LDG.128 coalesced)
    const float* src = feat + ((size_t)(b * S_ + j0)) * F_;
    #pragma unroll
    for (int p = 0; p < 4; p++) {
        int row = p * 8 + wrp;
        int col = lane * 4;
        float4 v = *reinterpret_cast<const float4*>(src + (size_t)row * F_ + col);
        tile[row][col] = v.x; tile[row][col + 1] = v.y;
        tile[row][col + 2] = v.z; tile[row][col + 3] = v.w;
    }
    __syncthreads();

    // variance: warp w handles rows 4w..4w+3
    float wm = 0.0f;
    float rres[4];
    #pragma unroll
    for (int g = 0; g < 4; g++) {
        int row = wrp * 4 + g;
        float4 v = *reinterpret_cast<const float4*>(&tile[row][lane * 4]);
        float s1 = v.x + v.y + v.z + v.w;
        float s2 = v.x * v.x + v.y * v.y + v.z * v.z + v.w * v.w;
        #pragma unroll
        for (int o = 16; o; o >>= 1) {
            s1 += __shfl_xor_sync(0xFFFFFFFFu, s1, o);
            s2 += __shfl_xor_sync(0xFFFFFFFFu, s2, o);
        }
        float var = (s2 - s1 * s1 * (1.0f / 128.0f)) * (1.0f / 127.0f);  // ddof=1
        float r = 1.0f / (var + 1e-6f);
        rres[g] = r;
        wm = fmaxf(wm, r);
    }
    if (lane == 0) {
        #pragma unroll
        for (int g = 0; g < 4; g++) g_sraw[b * S_ + j0 + wrp * 4 + g] = rres[g];
        atomicMax(&g_gmax, __float_as_int(wm));   // positive floats: int order ok
    }

    // transpose write: thread -> (f = t>>2 + 64p, 8 j's at jq*8), STG.128
    __half* dst = g_featT + (size_t)b * (F_ * S_);
    #pragma unroll
    for (int p = 0; p < 2; p++) {
        int f  = (t >> 2) + p * 64;
        int jq = t & 3;
        uint32_t h[4];
        #pragma unroll
        for (int i = 0; i < 4; i++)
            h[i] = pack_h2(tile[jq * 8 + 2 * i][f], tile[jq * 8 + 2 * i + 1][f]);
        *reinterpret_cast<uint4*>(dst + (size_t)f * S_ + j0 + jq * 8) =
            *reinterpret_cast<uint4*>(h);
    }
}

// ---------------------------------------------------------------------------
// Kernel 2: fused exp + fp16 mma.sync GEMM.
// 128 CTAs = (b, 128-row i-tile). 512 threads = 16 warps (4 i x 4 f),
// warp tile 32i x 32f. Noise: 2-deep register prefetch (LDG(kt+2) at stage
// kt, consumed by stage_P(kt+1)). featT: cp.async ring depth 3.
// ---------------------------------------------------------------------------
__global__ void __launch_bounds__(512, 1)
main_kernel(const float* __restrict__ noise, float* __restrict__ out) {
    extern __shared__ char smem[];
    float* rs_s = reinterpret_cast<float*>(smem + SMEM_RS);
    const uint32_t sbase = smem_u32(smem);
    const uint32_t Pbase = sbase + SMEM_P;
    const uint32_t Fbase = sbase + SMEM_F;

    const int tid  = threadIdx.x;
    const int lane = tid & 31;
    const int wid  = tid >> 5;        // 0..15
    const int wi   = wid >> 2;        // i block (32 rows): 0..3
    const int wf   = wid & 3;         // f block (32 cols): 0..3
    const int b    = blockIdx.x >> 4;
    const int i0   = (blockIdx.x & 15) * IT_ROWS;

    // staging map: thread owns row (tid>>2), k-chunk of 8 (cq)
    const int prow = tid >> 2;        // 0..127
    const int cq   = tid & 3;         // 0..3

    const uint32_t f_off = (uint32_t)(prow * FPITCH_B + cq * 16);
    const uint32_t p_off = (uint32_t)(prow * PPITCH_B + cq * 16);

    const float*  nsrc = noise + ((size_t)(b * S_ + i0 + prow)) * S_ + cq * 8;
    const __half* fsrc = g_featT + (size_t)b * (F_ * S_) + (size_t)prow * S_ + cq * 8;

    const float sl = g_sraw[b * S_ + i0 + prow] *
                     (1.0f / __int_as_float(g_gmax)) * LOG2E;
    float rs = 0.0f;

    // fragment lane offsets (fp16 m16n8k16)
    const uint32_t a_lane =
        (uint32_t)(((lane & 7) + ((lane >> 3) & 1) * 8) * PPITCH_B +
                   ((lane >> 4) & 1) * 16);
    const uint32_t b_lane =
        (uint32_t)((wf * 32 + (lane & 7) + ((lane >> 4) & 1) * 8) * FPITCH_B +
                   ((lane >> 3) & 1) * 16);

    float acc[2][4][4];
    #pragma unroll
    for (int it = 0; it < 2; it++)
        #pragma unroll
        for (int nb = 0; nb < 4; nb++)
            #pragma unroll
            for (int c = 0; c < 4; c++) acc[it][nb][c] = 0.0f;

    // noise register double-buffer: set j&1 holds chunk j
    float4 nv[2][2];

    auto ldg_noise = [&](int j) {   // chunk j -> set j&1
        if (j < NSTAGES) {
            nv[j & 1][0] = *reinterpret_cast<const float4*>(nsrc + (size_t)j * KC);
            nv[j & 1][1] = *reinterpret_cast<const float4*>(nsrc + (size_t)j * KC + 4);
        }
    };

    auto issue_F = [&](int j) {     // F(j) -> fbuf j%3
        if (j < NSTAGES) {
            const uint32_t fb = Fbase + (uint32_t)(j % 3) * F_BYTES;
            cp_async16(fb + f_off, fsrc + (size_t)j * KC);
        }
        CP_ASYNC_COMMIT();
    };

    auto stage_P = [&](int j) {     // exp(set j&1) -> P buf j&1
        const float4 v0 = nv[j & 1][0];
        const float4 v1 = nv[j & 1][1];
        float e0 = fast_ex2(v0.x * sl), e1 = fast_ex2(v0.y * sl);
        float e2 = fast_ex2(v0.z * sl), e3 = fast_ex2(v0.w * sl);
        float e4 = fast_ex2(v1.x * sl), e5 = fast_ex2(v1.y * sl);
        float e6 = fast_ex2(v1.z * sl), e7 = fast_ex2(v1.w * sl);
        rs += ((e0 + e1) + (e2 + e3)) + ((e4 + e5) + (e6 + e7));
        uint32_t h0 = pack_h2(e0, e1), h1 = pack_h2(e2, e3);
        uint32_t h2 = pack_h2(e4, e5), h3 = pack_h2(e6, e7);
        const uint32_t pb = Pbase + (uint32_t)(j & 1) * P_BYTES;
        asm volatile("st.shared.v4.b32 [%0], {%1,%2,%3,%4};"
                     :: "r"(pb + p_off), "r"(h0), "r"(h1), "r"(h2), "r"(h3));
    };

    // ---- prologue ----
    ldg_noise(0);
    ldg_noise(1);
    issue_F(0);
    issue_F(1);
    stage_P(0);
    CP_ASYNC_WAIT_1();   // F(0) done
    __syncthreads();

    // ---- mainloop ----
    for (int kt = 0; kt < NSTAGES; kt++) {
        ldg_noise(kt + 2);           // into set kt&1 (freed by stage_P(kt))
        issue_F(kt + 2);

        // MMA(kt): K=32 as two k16 steps
        {
            const uint32_t Pa = Pbase + (uint32_t)(kt & 1) * P_BYTES + a_lane
                              + (uint32_t)(wi * 32) * PPITCH_B;
            const uint32_t Fa = Fbase + (uint32_t)(kt % 3) * F_BYTES + b_lane;
            uint32_t A[2][2][4];
            #pragma unroll
            for (int it = 0; it < 2; it++)
                #pragma unroll
                for (int s = 0; s < 2; s++)
                    ldsm_x4(A[it][s], Pa + (uint32_t)(it * 16 * PPITCH_B + s * 32));
            #pragma unroll
            for (int p = 0; p < 2; p++) {        // n-block pairs (16 cols each)
                #pragma unroll
                for (int s = 0; s < 2; s++) {    // k16 steps
                    uint32_t bb[4];
                    ldsm_x4(bb, Fa + (uint32_t)(p * 16 * FPITCH_B + s * 32));
                    #pragma unroll
                    for (int it = 0; it < 2; it++) {
                        mma_f16(acc[it][2 * p],     A[it][s], bb[0], bb[1]);
                        mma_f16(acc[it][2 * p + 1], A[it][s], bb[2], bb[3]);
                    }
                }
            }
        }

        if (kt + 1 < NSTAGES) stage_P(kt + 1);

        CP_ASYNC_WAIT_1();   // F(kt+1) done
        __syncthreads();
    }

    // ---- row sums: 4 threads share a row ----
    rs += __shfl_xor_sync(0xFFFFFFFFu, rs, 1);
    rs += __shfl_xor_sync(0xFFFFFFFFu, rs, 2);
    if (cq == 0) rs_s[prow] = rs;
    __syncthreads();

    // ---- epilogue ----
    #pragma unroll
    for (int it = 0; it < 2; it++) {
        const int r0 = wi * 32 + it * 16 + (lane >> 2);
        const int r1 = r0 + 8;
        const float inv0 = 1.0f / rs_s[r0];
        const float inv1 = 1.0f / rs_s[r1];
        float* o0 = out + (size_t)(b * S_ + i0 + r0) * F_;
        float* o1 = out + (size_t)(b * S_ + i0 + r1) * F_;
        #pragma unroll
        for (int nb = 0; nb < 4; nb++) {
            const int n = wf * 32 + nb * 8 + (lane & 3) * 2;
            float2 v0 = { acc[it][nb][0] * inv0, acc[it][nb][1] * inv0 };
            float2 v1 = { acc[it][nb][2] * inv1, acc[it][nb][3] * inv1 };
            *reinterpret_cast<float2*>(o0 + n) = v0;
            *reinterpret_cast<float2*>(o1 + n) = v1;
        }
    }
}

// ---------------------------------------------------------------------------
// launch
// ---------------------------------------------------------------------------
extern "C" void kernel_launch(void* const* d_in, const int* in_sizes, int n_in,
                              void* d_out, int out_size) {
    static bool attr_set = false;
    if (!attr_set) {
        cudaFuncSetAttribute(main_kernel,
                             cudaFuncAttributeMaxDynamicSharedMemorySize, SMEM_TOTAL);
        attr_set = true;
    }

    const float* feature = (const float*)d_in[0];
    const float* noise   = (const float*)d_in[1];
    if (n_in >= 2 && in_sizes[0] > in_sizes[1]) {
        feature = (const float*)d_in[1];
        noise   = (const float*)d_in[0];
    }
    float* out = (float*)d_out;

    prep_kernel<<<dim3(S_ / 32, B_), 256>>>(feature);
    main_kernel<<<B_ * (S_ / IT_ROWS), 512, SMEM_TOTAL>>>(noise, out);
}